// round 17
// baseline (speedup 1.0000x reference)
#include <cuda_runtime.h>
#include <cuda_fp16.h>
#include <mma.h>
#include <cstdint>

using namespace nvcuda;

#define B_ROWS 32768
#define FDIM   512
#define NCOLS  1024
#define NCLS   1000

#define BM 128
#define BN 128
#define BK 64
#define LDA 72               // fp16 smem pitch (144B, conflict-free LDSM)
#define LDE 136              // fp32 epilogue pitch
#define NIT 8                // 512/64
#define TILE_B 18432         // one 128x64 fp16 tile @ 144B pitch
#define STAGE_BYTES 36864    // Ah + Wh
#define NSTAGE 3
#define SMEM_GEMM (NSTAGE * STAGE_BYTES)   // 110592 (>= epilogue 69632)

#define NCHUNK 4
#define CROWS  (B_ROWS / NCHUNK)

// scatter: 4-row tile -> 6 CTAs/SM (measured best)
#define SROWS 4
#define SC_WSM 0
#define SC_OFF 16384
#define SC_SRC 20488
#define SMEM_SCAT 24584

__device__ int    g_cls_off[NCLS + 1];
__device__ int    g_cls_src[NCOLS];
__device__ __half g_Ah[(size_t)B_ROWS * FDIM];
__device__ __half g_Wh[NCOLS * FDIM];
__device__ float  g_scratch[(size_t)B_ROWS * NCOLS];

__device__ __forceinline__ uint32_t smem_u32(const void* p) {
    uint32_t a;
    asm("{ .reg .u64 t; cvta.to.shared.u64 t, %1; cvt.u32.u64 %0, t; }" : "=r"(a) : "l"(p));
    return a;
}
__device__ __forceinline__ void cp16(uint32_t dst, const void* src) {
    asm volatile("cp.async.cg.shared.global [%0], [%1], 16;" :: "r"(dst), "l"(src) : "memory");
}

// ---- prep: deterministic CSR (atomic fill + per-class sort == sequential order) ----
__global__ void prep_kernel(const int* __restrict__ label_ids) {
    __shared__ int lab[NCOLS];
    __shared__ int cnt[NCLS];
    __shared__ int off[NCLS + 1];
    __shared__ int pos[NCLS];
    __shared__ int srcs[NCOLS];
    int t = threadIdx.x;
    lab[t] = label_ids[t];
    if (t < NCLS) cnt[t] = 0;
    __syncthreads();
    atomicAdd(&cnt[lab[t]], 1);
    __syncthreads();
    if (t == 0) {
        int a = 0;
        for (int c = 0; c < NCLS; c++) { off[c] = a; a += cnt[c]; }
        off[NCLS] = a;
    }
    __syncthreads();
    if (t < NCLS) pos[t] = off[t];
    __syncthreads();
    int p = atomicAdd(&pos[lab[t]], 1);
    srcs[p] = t;
    __syncthreads();
    if (t < NCLS) {
        int s0 = off[t], s1 = off[t + 1];
        for (int i = s0 + 1; i < s1; i++) {
            int v = srcs[i], j = i - 1;
            while (j >= s0 && srcs[j] > v) { srcs[j + 1] = srcs[j]; j--; }
            srcs[j + 1] = v;
        }
    }
    __syncthreads();
    if (t <= NCLS) g_cls_off[t] = off[t];
    g_cls_src[t] = srcs[t];
}

// ---- prep: fp32 -> fp16 (W whole, A per chunk) ----
__global__ void prep_w16(const float* __restrict__ W, __half* __restrict__ Wh) {
    size_t i0 = ((size_t)blockIdx.x * 256 + threadIdx.x) * 4;
    float4 v = *(const float4*)(W + i0);
    __half h[4];
    h[0] = __float2half_rn(v.x);
    h[1] = __float2half_rn(v.y);
    h[2] = __float2half_rn(v.z);
    h[3] = __float2half_rn(v.w);
    *(uint2*)(Wh + i0) = *(uint2*)h;
}

__global__ void prep_a16(const float* __restrict__ A, __half* __restrict__ Ah, int rbase) {
    size_t i0 = (size_t)rbase * FDIM + ((size_t)blockIdx.x * 256 + threadIdx.x) * 4;
    float4 v = *(const float4*)(A + i0);
    __half h[4];
    h[0] = __float2half_rn(v.x);
    h[1] = __float2half_rn(v.y);
    h[2] = __float2half_rn(v.z);
    h[3] = __float2half_rn(v.w);
    *(uint2*)(Ah + i0) = *(uint2*)h;
}

// ---- GEMM: 128x128 fp16, BK=64, 3-stage cp.async ring (2-sync schedule) ----
__global__ void __launch_bounds__(256, 2)
mhc_gemm(const float* __restrict__ gprob, const float* __restrict__ bias, int rbase) {
    extern __shared__ char smem[];
    const uint32_t sb = smem_u32(smem);
    const int t   = threadIdx.x;
    const int wid = t >> 5;
    const int n0   = blockIdx.x * BN;
    const int row0 = rbase + blockIdx.y * BM;
    const int wm0 = (wid & 3) * 32;
    const int wn0 = (wid >> 2) * 64;

    wmma::fragment<wmma::accumulator, 16, 16, 16, float> acc[2][4];
#pragma unroll
    for (int fm = 0; fm < 2; fm++)
#pragma unroll
        for (int fn = 0; fn < 4; fn++) wmma::fill_fragment(acc[fm][fn], 0.0f);

    auto issue = [&](int it) {
        if (it < NIT) {
            int s = it % NSTAGE;
            const char* ah = (const char*)(g_Ah + (size_t)row0 * FDIM + it * BK);
            const char* wh = (const char*)(g_Wh + (size_t)n0 * FDIM + it * BK);
            uint32_t st = sb + s * STAGE_BYTES;
#pragma unroll
            for (int i = 0; i < 4; i++) {
                int id = i * 256 + t;
                int r = id >> 3, co = (id & 7) * 16;
                size_t go = (size_t)r * 1024 + co;
                uint32_t so = r * 144 + co;
                cp16(st + so,          ah + go);
                cp16(st + TILE_B + so, wh + go);
            }
        }
        asm volatile("cp.async.commit_group;" ::: "memory");
    };

    issue(0);
    issue(1);
    for (int it = 0; it < NIT; ++it) {
        int s = it % NSTAGE;
        issue(it + 2);      // overwrites stage (it-1)%3: freed by trailing sync of it-1
        asm volatile("cp.async.wait_group 2;" ::: "memory");   // stage `it` complete
        __syncthreads();    // collective: all threads' copies for stage `it` landed

        const __half* ah_sm = (const __half*)(smem + s * STAGE_BYTES);
        const __half* wh_sm = (const __half*)(smem + s * STAGE_BYTES + TILE_B);
#pragma unroll
        for (int kk = 0; kk < BK; kk += 16) {
            wmma::fragment<wmma::matrix_a, 16, 16, 16, __half, wmma::row_major> afh[2];
            wmma::fragment<wmma::matrix_b, 16, 16, 16, __half, wmma::col_major> bfh[4];
#pragma unroll
            for (int fm = 0; fm < 2; fm++)
                wmma::load_matrix_sync(afh[fm], ah_sm + (wm0 + fm * 16) * LDA + kk, LDA);
#pragma unroll
            for (int fn = 0; fn < 4; fn++)
                wmma::load_matrix_sync(bfh[fn], wh_sm + (wn0 + fn * 16) * LDA + kk, LDA);
#pragma unroll
            for (int fm = 0; fm < 2; fm++)
#pragma unroll
                for (int fn = 0; fn < 4; fn++)
                    wmma::mma_sync(acc[fm][fn], afh[fm], bfh[fn], acc[fm][fn]);
        }
        __syncthreads();    // all warps done reading stage `it` before it+3 overwrites
    }

    // ---- epilogue: frags -> smem -> (bias+gprob) -> scratch (coalesced f4) ----
    float* epi = (float*)smem;
#pragma unroll
    for (int fm = 0; fm < 2; fm++)
#pragma unroll
        for (int fn = 0; fn < 4; fn++)
            wmma::store_matrix_sync(epi + (wm0 + fm * 16) * LDE + wn0 + fn * 16,
                                    acc[fm][fn], LDE, wmma::mem_row_major);
    __syncthreads();

#pragma unroll
    for (int i = 0; i < 16; i++) {
        int idx = i * 256 + t;
        int r  = idx >> 5;
        int c4 = (idx & 31) * 4;
        float4 v = *(float4*)(epi + r * LDE + c4);
        int n = n0 + c4;
        float gp = __ldg(gprob + (size_t)(row0 + r) * 16 + (n >> 6));
        v.x = (v.x + __ldg(bias + n + 0)) * gp;
        v.y = (v.y + __ldg(bias + n + 1)) * gp;
        v.z = (v.z + __ldg(bias + n + 2)) * gp;
        v.w = (v.w + __ldg(bias + n + 3)) * gp;
        *(float4*)(g_scratch + (size_t)(row0 + r) * NCOLS + n) = v;
    }
}

// ---- scatter: 4-row tiles, 6 CTAs/SM, class-outer/row-inner gather ----
__global__ void __launch_bounds__(256, 6)
mhc_scatter(float* __restrict__ out, int rbase) {
    extern __shared__ char smem[];
    float* wsm    = (float*)(smem + SC_WSM);
    int*   off_sm = (int*)(smem + SC_OFF);
    int*   src_sm = (int*)(smem + SC_SRC);
    const int t = threadIdx.x;
    const int r0 = rbase + blockIdx.x * SROWS;

    for (int i = t; i <= NCLS; i += 256) off_sm[i] = g_cls_off[i];
    for (int i = t; i < NCOLS; i += 256) src_sm[i] = g_cls_src[i];

    const float4* src = (const float4*)(g_scratch + (size_t)r0 * NCOLS);
    float4* dst4 = (float4*)wsm;
#pragma unroll
    for (int i = 0; i < SROWS * NCOLS / 4 / 256; i++)
        dst4[i * 256 + t] = src[i * 256 + t];
    __syncthreads();

    for (int c = t; c < NCLS; c += 256) {
        int s0 = off_sm[c], s1 = off_sm[c + 1];
        float* ocol = out + (size_t)r0 * NCLS + c;
        if (s1 == s0) {
#pragma unroll
            for (int r = 0; r < SROWS; r++) ocol[(size_t)r * NCLS] = 0.f;
        } else if (s1 == s0 + 1) {
            int src0 = src_sm[s0];
#pragma unroll
            for (int r = 0; r < SROWS; r++)
                ocol[(size_t)r * NCLS] = wsm[r * NCOLS + src0];
        } else {
#pragma unroll
            for (int r = 0; r < SROWS; r++) {
                float s = 0.f;
                for (int k = s0; k < s1; k++) s += wsm[r * NCOLS + src_sm[k]];
                ocol[(size_t)r * NCLS] = s;
            }
        }
    }
}

extern "C" void kernel_launch(void* const* d_in, const int* in_sizes, int n_in,
                              void* d_out, int out_size) {
    const float* features = (const float*)d_in[0];
    const float* gprob    = (const float*)d_in[1];
    const float* W        = (const float*)d_in[2];
    const float* bias     = (const float*)d_in[3];
    const int*   labels   = (const int*)d_in[4];
    float* out = (float*)d_out;

    static __half *hA, *hW;
    static cudaStream_t s2, sG;
    static cudaEvent_t evF, evS, evG[NCHUNK], evJ, evJG;
    static bool init = false;
    if (!init) {
        cudaGetSymbolAddress((void**)&hA, g_Ah);
        cudaGetSymbolAddress((void**)&hW, g_Wh);
        cudaFuncSetAttribute(mhc_gemm, cudaFuncAttributeMaxDynamicSharedMemorySize, SMEM_GEMM);
        cudaFuncSetAttribute(mhc_scatter, cudaFuncAttributeMaxDynamicSharedMemorySize, SMEM_SCAT);
        cudaStreamCreateWithFlags(&s2, cudaStreamNonBlocking);
        cudaStreamCreateWithFlags(&sG, cudaStreamNonBlocking);
        cudaEventCreateWithFlags(&evF, cudaEventDisableTiming);
        cudaEventCreateWithFlags(&evS, cudaEventDisableTiming);
        for (int c = 0; c < NCHUNK; c++)
            cudaEventCreateWithFlags(&evG[c], cudaEventDisableTiming);
        cudaEventCreateWithFlags(&evJ, cudaEventDisableTiming);
        cudaEventCreateWithFlags(&evJG, cudaEventDisableTiming);
        init = true;
    }

    // fork: side stream runs the (independent) CSR prep
    cudaEventRecord(evF, 0);
    cudaStreamWaitEvent(s2, evF, 0);
    prep_kernel<<<1, 1024, 0, s2>>>(labels);

    // W convert on sG concurrent with chunk-0 A convert on stream 0
    cudaStreamWaitEvent(sG, evF, 0);
    prep_w16<<<(NCOLS * FDIM) / 1024, 256, 0, sG>>>(W, hW);
    cudaEventRecord(evS, sG);
    cudaStreamWaitEvent(0, evS, 0);   // GEMM chunks on stream 0 need W ready

    for (int c = 0; c < NCHUNK; c++) {
        cudaStream_t gs = (c & 1) ? sG : 0;
        prep_a16<<<(CROWS * FDIM) / 1024, 256, 0, gs>>>(features, hA, c * CROWS);
        dim3 grid(NCOLS / BN, CROWS / BM);
        mhc_gemm<<<grid, 256, SMEM_GEMM, gs>>>(gprob, bias, c * CROWS);
        cudaEventRecord(evG[c], gs);
        cudaStreamWaitEvent(s2, evG[c], 0);
        mhc_scatter<<<CROWS / SROWS, 256, SMEM_SCAT, s2>>>(out, c * CROWS);
    }

    // join both side streams back into stream 0
    cudaEventRecord(evJ, s2);
    cudaStreamWaitEvent(0, evJ, 0);
    cudaEventRecord(evJG, sG);
    cudaStreamWaitEvent(0, evJG, 0);
}